// round 9
// baseline (speedup 1.0000x reference)
#include <cuda_runtime.h>

// ACT-LSTM persistent kernel, v5.
// vs v4: full-chip grid (148 blocks) with BLOCK-INTERLEAVED row assignment
//   r = blockIdx + 148*warp (+4736), giving every SM 55-56 rows (balanced
//   within 1.8%) instead of 20 idle SMs / 2:1 block imbalance.
//   Epilogue likewise spread over all 148 blocks (k-quartered rows).
//
// I=1024, H=2048, O=1024, 4H=8192, MAX_STEPS=20.

#define NBLOCK 148
#define NTHREAD 1024
#define WPB (NTHREAD / 32)            // 32 warps/block
#define NWARP (NBLOCK * WPB)          // 4736
#define HDIM 2048
#define IDIM 1024
#define ODIM 1024
#define G4 (4 * HDIM)                 // 8192
#define MAX_STEPS 20

// -------- device scratch (no allocation allowed) --------
__device__ float g_gates[2][G4];      // double-buffered gate pre-activations
__device__ float g_gx_buf[G4];        // W_ih[:,1:]@x + b_ih + b_hh (step-invariant)

// -------- manual grid barrier --------
__device__ unsigned g_bar_count = 0;
__device__ volatile unsigned g_bar_gen = 0;

__device__ __forceinline__ void grid_sync() {
    __syncthreads();
    if (threadIdx.x == 0) {
        __threadfence();
        unsigned gen = g_bar_gen;
        if (atomicAdd(&g_bar_count, 1u) == NBLOCK - 1) {
            g_bar_count = 0u;
            __threadfence();
            g_bar_gen = gen + 1u;
        } else {
            while (g_bar_gen == gen) { __nanosleep(32); }
            __threadfence();
        }
    }
    __syncthreads();
}

__device__ __forceinline__ float warp_reduce(float v) {
    #pragma unroll
    for (int off = 16; off; off >>= 1) v += __shfl_xor_sync(0xffffffffu, v, off);
    return v;
}

__device__ __forceinline__ float sigmoidf_(float x) {
    return 1.0f / (1.0f + __expf(-x));
}

__global__ __launch_bounds__(NTHREAD, 1)
void act_lstm_kernel(const float* __restrict__ x,
                     const float* __restrict__ h0,
                     const float* __restrict__ c0,
                     const float* __restrict__ W_ih,
                     const float* __restrict__ W_hh,
                     const float* __restrict__ b_ih,
                     const float* __restrict__ b_hh,
                     const float* __restrict__ w_halt,
                     const float* __restrict__ b_halt,
                     const float* __restrict__ W_out,
                     const float* __restrict__ b_out,
                     float* __restrict__ out) {
    __shared__ float sh_h[HDIM];
    __shared__ float sh_c[HDIM];
    __shared__ float sh_x[IDIM];
    __shared__ float s_red[WPB];

    const int tid  = threadIdx.x;
    const int lane = tid & 31;
    const int warp = tid >> 5;
    const int rbase = blockIdx.x + NBLOCK * warp;   // block-interleaved rows

    // ---- init block-local state ----
    for (int j = tid; j < HDIM; j += NTHREAD) {
        sh_h[j] = h0[j];
        sh_c[j] = c0[j];
    }
    if (tid < IDIM) sh_x[tid] = x[tid];
    const float bh = b_halt[0];
    __syncthreads();

    // ---- fused phase: gates(t=0) = W_ih@[1,x] + b_ih + b_hh + W_hh@h0 ----
    for (int r = rbase; r < G4; r += NWARP) {
        const float* wi = W_ih + (size_t)r * (IDIM + 1);
        float ai0 = 0.f, ai1 = 0.f;
        #pragma unroll 4
        for (int k = lane; k < IDIM; k += 64) {
            ai0 += __ldg(wi + 1 + k) * sh_x[k];
            ai1 += __ldg(wi + 1 + k + 32) * sh_x[k + 32];
        }

        const float4* wh = (const float4*)(W_hh + (size_t)r * HDIM);
        const float4* hv = (const float4*)sh_h;
        float ah0 = 0.f, ah1 = 0.f;
        #pragma unroll 4
        for (int k = lane; k < HDIM / 4; k += 64) {
            float4 w0 = __ldg(wh + k);
            float4 h4 = hv[k];
            float4 w1 = __ldg(wh + k + 32);
            float4 h5 = hv[k + 32];
            ah0 += w0.x * h4.x + w0.y * h4.y + w0.z * h4.z + w0.w * h4.w;
            ah1 += w1.x * h5.x + w1.y * h5.y + w1.z * h5.z + w1.w * h5.w;
        }

        float ai = warp_reduce(ai0 + ai1);
        float ah = warp_reduce(ah0 + ah1);
        if (lane == 0) {
            float base = ai + b_ih[r] + b_hh[r];
            g_gx_buf[r] = base;
            g_gates[0][r] = base + wi[0] + ah;   // flag column active at t=0
        }
    }
    grid_sync();

    // ---- adaptive loop: ONE grid barrier per step ----
    float cum = 0.0f;
    int   halted_t = MAX_STEPS - 1;
    int   buf = 0;

    for (int t = 0; t < MAX_STEPS; ++t) {
        // phase B: activations + halt (redundant per block, block-local state)
        const float* gt = g_gates[buf];
        float part = 0.0f;
        #pragma unroll
        for (int j = tid; j < HDIM; j += NTHREAD) {
            float gi = gt[j];
            float gf = gt[HDIM + j];
            float gg = gt[2 * HDIM + j];
            float go = gt[3 * HDIM + j];
            float cn = sigmoidf_(gf) * sh_c[j] + sigmoidf_(gi) * tanhf(gg);
            float hn = sigmoidf_(go) * tanhf(cn);
            sh_c[j] = cn;
            sh_h[j] = hn;
            part += w_halt[j] * hn;
        }
        part = warp_reduce(part);
        if (lane == 0) s_red[warp] = part;
        __syncthreads();
        float dot = 0.0f;
        #pragma unroll
        for (int w2 = 0; w2 < WPB; ++w2) dot += s_red[w2];
        float p = sigmoidf_(dot + bh);
        cum += p;
        if (cum >= 0.99f || t == MAX_STEPS - 1) { halted_t = t; break; }

        // phase A for step t+1: gates = gx + W_hh @ h
        buf ^= 1;
        float* gn = g_gates[buf];
        for (int r = rbase; r < G4; r += NWARP) {
            const float4* wh = (const float4*)(W_hh + (size_t)r * HDIM);
            const float4* hv = (const float4*)sh_h;
            float ah0 = 0.f, ah1 = 0.f;
            #pragma unroll 4
            for (int k = lane; k < HDIM / 4; k += 64) {
                float4 w0 = __ldg(wh + k);
                float4 h4 = hv[k];
                float4 w1 = __ldg(wh + k + 32);
                float4 h5 = hv[k + 32];
                ah0 += w0.x * h4.x + w0.y * h4.y + w0.z * h4.z + w0.w * h4.w;
                ah1 += w1.x * h5.x + w1.y * h5.y + w1.z * h5.z + w1.w * h5.w;
            }
            float ah = warp_reduce(ah0 + ah1);
            if (lane == 0) gn[r] = g_gx_buf[r] + ah;
        }
        grid_sync();
    }

    // ---- epilogue (barrier-free): out = W_out @ h + b_out ----
    // row = blockIdx + 148*j, j = warp/4; each of 4 warps does a k-quarter.
    __syncthreads();
    {
        const int j   = warp >> 2;                   // 0..7
        const int q   = warp & 3;
        const int row = blockIdx.x + NBLOCK * j;     // < 1024 for j <= 6 (mostly)
        float a = 0.f;
        if (row < ODIM) {
            const float4* wr = (const float4*)(W_out + (size_t)row * HDIM) + q * (HDIM / 16);
            const float4* hv = (const float4*)sh_h + q * (HDIM / 16);
            #pragma unroll 4
            for (int k = lane; k < HDIM / 16; k += 32) {   // 128 float4 per quarter
                float4 w  = __ldg(wr + k);
                float4 h4 = hv[k];
                a += w.x * h4.x + w.y * h4.y + w.z * h4.z + w.w * h4.w;
            }
            a = warp_reduce(a);
        }
        if (lane == 0) s_red[warp] = a;
        __syncthreads();
        if ((warp & 3) == 0 && row < ODIM && lane == 0) {
            out[row] = s_red[warp] + s_red[warp + 1] + s_red[warp + 2]
                     + s_red[warp + 3] + b_out[row];
        }
    }

    if (blockIdx.x == 0) {
        for (int j = tid; j < HDIM; j += NTHREAD) {
            out[ODIM + j]        = sh_h[j];
            out[ODIM + HDIM + j] = sh_c[j];
        }
        if (tid == 0) out[ODIM + 2 * HDIM] = (float)halted_t;
    }
}

extern "C" void kernel_launch(void* const* d_in, const int* in_sizes, int n_in,
                              void* d_out, int out_size) {
    (void)in_sizes; (void)n_in; (void)out_size;
    const float* x      = (const float*)d_in[0];
    const float* h0     = (const float*)d_in[1];
    const float* c0     = (const float*)d_in[2];
    const float* W_ih   = (const float*)d_in[3];
    const float* W_hh   = (const float*)d_in[4];
    const float* b_ih   = (const float*)d_in[5];
    const float* b_hh   = (const float*)d_in[6];
    const float* w_halt = (const float*)d_in[7];
    const float* b_halt = (const float*)d_in[8];
    const float* W_out  = (const float*)d_in[9];
    const float* b_out  = (const float*)d_in[10];
    float* out = (float*)d_out;

    act_lstm_kernel<<<NBLOCK, NTHREAD>>>(x, h0, c0, W_ih, W_hh, b_ih, b_hh,
                                         w_halt, b_halt, W_out, b_out, out);
}

// round 10
// speedup vs baseline: 1.0427x; 1.0427x over previous
#include <cuda_runtime.h>

// ACT-LSTM persistent kernel, v5.
// vs v4: full-chip grid (148 blocks) with BLOCK-INTERLEAVED row assignment
//   r = blockIdx + 148*warp (+4736), giving every SM 55-56 rows (balanced
//   within 1.8%) instead of 20 idle SMs / 2:1 block imbalance.
//   Epilogue likewise spread over all 148 blocks (k-quartered rows).
//
// I=1024, H=2048, O=1024, 4H=8192, MAX_STEPS=20.

#define NBLOCK 148
#define NTHREAD 1024
#define WPB (NTHREAD / 32)            // 32 warps/block
#define NWARP (NBLOCK * WPB)          // 4736
#define HDIM 2048
#define IDIM 1024
#define ODIM 1024
#define G4 (4 * HDIM)                 // 8192
#define MAX_STEPS 20

// -------- device scratch (no allocation allowed) --------
__device__ float g_gates[2][G4];      // double-buffered gate pre-activations
__device__ float g_gx_buf[G4];        // W_ih[:,1:]@x + b_ih + b_hh (step-invariant)

// -------- manual grid barrier --------
__device__ unsigned g_bar_count = 0;
__device__ volatile unsigned g_bar_gen = 0;

__device__ __forceinline__ void grid_sync() {
    __syncthreads();
    if (threadIdx.x == 0) {
        __threadfence();
        unsigned gen = g_bar_gen;
        if (atomicAdd(&g_bar_count, 1u) == NBLOCK - 1) {
            g_bar_count = 0u;
            __threadfence();
            g_bar_gen = gen + 1u;
        } else {
            while (g_bar_gen == gen) { __nanosleep(32); }
            __threadfence();
        }
    }
    __syncthreads();
}

__device__ __forceinline__ float warp_reduce(float v) {
    #pragma unroll
    for (int off = 16; off; off >>= 1) v += __shfl_xor_sync(0xffffffffu, v, off);
    return v;
}

__device__ __forceinline__ float sigmoidf_(float x) {
    return 1.0f / (1.0f + __expf(-x));
}

__global__ __launch_bounds__(NTHREAD, 1)
void act_lstm_kernel(const float* __restrict__ x,
                     const float* __restrict__ h0,
                     const float* __restrict__ c0,
                     const float* __restrict__ W_ih,
                     const float* __restrict__ W_hh,
                     const float* __restrict__ b_ih,
                     const float* __restrict__ b_hh,
                     const float* __restrict__ w_halt,
                     const float* __restrict__ b_halt,
                     const float* __restrict__ W_out,
                     const float* __restrict__ b_out,
                     float* __restrict__ out) {
    __shared__ float sh_h[HDIM];
    __shared__ float sh_c[HDIM];
    __shared__ float sh_x[IDIM];
    __shared__ float s_red[WPB];

    const int tid  = threadIdx.x;
    const int lane = tid & 31;
    const int warp = tid >> 5;
    const int rbase = blockIdx.x + NBLOCK * warp;   // block-interleaved rows

    // ---- init block-local state ----
    for (int j = tid; j < HDIM; j += NTHREAD) {
        sh_h[j] = h0[j];
        sh_c[j] = c0[j];
    }
    if (tid < IDIM) sh_x[tid] = x[tid];
    const float bh = b_halt[0];
    __syncthreads();

    // ---- fused phase: gates(t=0) = W_ih@[1,x] + b_ih + b_hh + W_hh@h0 ----
    for (int r = rbase; r < G4; r += NWARP) {
        const float* wi = W_ih + (size_t)r * (IDIM + 1);
        float ai0 = 0.f, ai1 = 0.f;
        #pragma unroll 4
        for (int k = lane; k < IDIM; k += 64) {
            ai0 += __ldg(wi + 1 + k) * sh_x[k];
            ai1 += __ldg(wi + 1 + k + 32) * sh_x[k + 32];
        }

        const float4* wh = (const float4*)(W_hh + (size_t)r * HDIM);
        const float4* hv = (const float4*)sh_h;
        float ah0 = 0.f, ah1 = 0.f;
        #pragma unroll 4
        for (int k = lane; k < HDIM / 4; k += 64) {
            float4 w0 = __ldg(wh + k);
            float4 h4 = hv[k];
            float4 w1 = __ldg(wh + k + 32);
            float4 h5 = hv[k + 32];
            ah0 += w0.x * h4.x + w0.y * h4.y + w0.z * h4.z + w0.w * h4.w;
            ah1 += w1.x * h5.x + w1.y * h5.y + w1.z * h5.z + w1.w * h5.w;
        }

        float ai = warp_reduce(ai0 + ai1);
        float ah = warp_reduce(ah0 + ah1);
        if (lane == 0) {
            float base = ai + b_ih[r] + b_hh[r];
            g_gx_buf[r] = base;
            g_gates[0][r] = base + wi[0] + ah;   // flag column active at t=0
        }
    }
    grid_sync();

    // ---- adaptive loop: ONE grid barrier per step ----
    float cum = 0.0f;
    int   halted_t = MAX_STEPS - 1;
    int   buf = 0;

    for (int t = 0; t < MAX_STEPS; ++t) {
        // phase B: activations + halt (redundant per block, block-local state)
        const float* gt = g_gates[buf];
        float part = 0.0f;
        #pragma unroll
        for (int j = tid; j < HDIM; j += NTHREAD) {
            float gi = gt[j];
            float gf = gt[HDIM + j];
            float gg = gt[2 * HDIM + j];
            float go = gt[3 * HDIM + j];
            float cn = sigmoidf_(gf) * sh_c[j] + sigmoidf_(gi) * tanhf(gg);
            float hn = sigmoidf_(go) * tanhf(cn);
            sh_c[j] = cn;
            sh_h[j] = hn;
            part += w_halt[j] * hn;
        }
        part = warp_reduce(part);
        if (lane == 0) s_red[warp] = part;
        __syncthreads();
        float dot = 0.0f;
        #pragma unroll
        for (int w2 = 0; w2 < WPB; ++w2) dot += s_red[w2];
        float p = sigmoidf_(dot + bh);
        cum += p;
        if (cum >= 0.99f || t == MAX_STEPS - 1) { halted_t = t; break; }

        // phase A for step t+1: gates = gx + W_hh @ h
        buf ^= 1;
        float* gn = g_gates[buf];
        for (int r = rbase; r < G4; r += NWARP) {
            const float4* wh = (const float4*)(W_hh + (size_t)r * HDIM);
            const float4* hv = (const float4*)sh_h;
            float ah0 = 0.f, ah1 = 0.f;
            #pragma unroll 4
            for (int k = lane; k < HDIM / 4; k += 64) {
                float4 w0 = __ldg(wh + k);
                float4 h4 = hv[k];
                float4 w1 = __ldg(wh + k + 32);
                float4 h5 = hv[k + 32];
                ah0 += w0.x * h4.x + w0.y * h4.y + w0.z * h4.z + w0.w * h4.w;
                ah1 += w1.x * h5.x + w1.y * h5.y + w1.z * h5.z + w1.w * h5.w;
            }
            float ah = warp_reduce(ah0 + ah1);
            if (lane == 0) gn[r] = g_gx_buf[r] + ah;
        }
        grid_sync();
    }

    // ---- epilogue (barrier-free): out = W_out @ h + b_out ----
    // row = blockIdx + 148*j, j = warp/4; each of 4 warps does a k-quarter.
    __syncthreads();
    {
        const int j   = warp >> 2;                   // 0..7
        const int q   = warp & 3;
        const int row = blockIdx.x + NBLOCK * j;     // < 1024 for j <= 6 (mostly)
        float a = 0.f;
        if (row < ODIM) {
            const float4* wr = (const float4*)(W_out + (size_t)row * HDIM) + q * (HDIM / 16);
            const float4* hv = (const float4*)sh_h + q * (HDIM / 16);
            #pragma unroll 4
            for (int k = lane; k < HDIM / 16; k += 32) {   // 128 float4 per quarter
                float4 w  = __ldg(wr + k);
                float4 h4 = hv[k];
                a += w.x * h4.x + w.y * h4.y + w.z * h4.z + w.w * h4.w;
            }
            a = warp_reduce(a);
        }
        if (lane == 0) s_red[warp] = a;
        __syncthreads();
        if ((warp & 3) == 0 && row < ODIM && lane == 0) {
            out[row] = s_red[warp] + s_red[warp + 1] + s_red[warp + 2]
                     + s_red[warp + 3] + b_out[row];
        }
    }

    if (blockIdx.x == 0) {
        for (int j = tid; j < HDIM; j += NTHREAD) {
            out[ODIM + j]        = sh_h[j];
            out[ODIM + HDIM + j] = sh_c[j];
        }
        if (tid == 0) out[ODIM + 2 * HDIM] = (float)halted_t;
    }
}

extern "C" void kernel_launch(void* const* d_in, const int* in_sizes, int n_in,
                              void* d_out, int out_size) {
    (void)in_sizes; (void)n_in; (void)out_size;
    const float* x      = (const float*)d_in[0];
    const float* h0     = (const float*)d_in[1];
    const float* c0     = (const float*)d_in[2];
    const float* W_ih   = (const float*)d_in[3];
    const float* W_hh   = (const float*)d_in[4];
    const float* b_ih   = (const float*)d_in[5];
    const float* b_hh   = (const float*)d_in[6];
    const float* w_halt = (const float*)d_in[7];
    const float* b_halt = (const float*)d_in[8];
    const float* W_out  = (const float*)d_in[9];
    const float* b_out  = (const float*)d_in[10];
    float* out = (float*)d_out;

    act_lstm_kernel<<<NBLOCK, NTHREAD>>>(x, h0, c0, W_ih, W_hh, b_ih, b_hh,
                                         w_halt, b_halt, W_out, b_out, out);
}

// round 11
// speedup vs baseline: 1.1056x; 1.0603x over previous
#include <cuda_runtime.h>

// ACT-LSTM persistent kernel, v6.
// vs v4/v5: QUARTER-ROW work units. Each block owns 55-56 contiguous gate
// rows; each row is 4 units (512 W_hh + 256 W_ih floats). 56*4 = 224 units
// over 32 warps = exactly 7/warp -> critical path 1.75 rows (v4: 2.0) on all
// 148 SMs. Unit loads are issued as one flat batch (4 LDG.128 + 8 LDG.32)
// for high MLP. Quarter partials combined via shared memory, fixed order.
//
// I=1024, H=2048, O=1024, 4H=8192, MAX_STEPS=20.

#define NBLOCK 148
#define NTHREAD 1024
#define WPB 32
#define HDIM 2048
#define IDIM 1024
#define ODIM 1024
#define G4 (4 * HDIM)                 // 8192
#define MAX_STEPS 20
#define MAXROWS 56                    // max rows per block
#define MAXUNITS (MAXROWS * 4)        // 224

// -------- device scratch --------
__device__ float g_gates[2][G4];
__device__ float g_gx_buf[G4];

// -------- manual grid barrier --------
__device__ unsigned g_bar_count = 0;
__device__ volatile unsigned g_bar_gen = 0;

__device__ __forceinline__ void grid_sync() {
    __syncthreads();
    if (threadIdx.x == 0) {
        __threadfence();
        unsigned gen = g_bar_gen;
        if (atomicAdd(&g_bar_count, 1u) == NBLOCK - 1) {
            g_bar_count = 0u;
            __threadfence();
            g_bar_gen = gen + 1u;
        } else {
            while (g_bar_gen == gen) { __nanosleep(32); }
            __threadfence();
        }
    }
    __syncthreads();
}

__device__ __forceinline__ float warp_reduce(float v) {
    #pragma unroll
    for (int off = 16; off; off >>= 1) v += __shfl_xor_sync(0xffffffffu, v, off);
    return v;
}

__device__ __forceinline__ float sigmoidf_(float x) {
    return 1.0f / (1.0f + __expf(-x));
}

__device__ __forceinline__ float dot4(float4 a, float4 b) {
    return a.x * b.x + a.y * b.y + a.z * b.z + a.w * b.w;
}

__global__ __launch_bounds__(NTHREAD, 1)
void act_lstm_kernel(const float* __restrict__ x,
                     const float* __restrict__ h0,
                     const float* __restrict__ c0,
                     const float* __restrict__ W_ih,
                     const float* __restrict__ W_hh,
                     const float* __restrict__ b_ih,
                     const float* __restrict__ b_hh,
                     const float* __restrict__ w_halt,
                     const float* __restrict__ b_halt,
                     const float* __restrict__ W_out,
                     const float* __restrict__ b_out,
                     float* __restrict__ out) {
    __shared__ float sh_h[HDIM];
    __shared__ float sh_c[HDIM];
    __shared__ float sh_x[IDIM];
    __shared__ float s_ih[MAXUNITS];
    __shared__ float s_hh[MAXUNITS];
    __shared__ float s_red[WPB];

    const int tid  = threadIdx.x;
    const int lane = tid & 31;
    const int warp = tid >> 5;
    const int bx   = blockIdx.x;

    // row chunk for this block: 52 blocks get 56 rows, 96 get 55
    const int nrows  = 55 + (bx < 52 ? 1 : 0);
    const int chunk  = bx * 55 + (bx < 52 ? bx : 52);
    const int nunits = nrows * 4;

    // ---- init block-local state ----
    for (int j = tid; j < HDIM; j += NTHREAD) {
        sh_h[j] = h0[j];
        sh_c[j] = c0[j];
    }
    if (tid < IDIM) sh_x[tid] = x[tid];
    const float bh = b_halt[0];
    __syncthreads();

    // ---- fused phase: gates(t=0) = W_ih@[1,x] + b_ih + b_hh + W_hh@h0 ----
    for (int u = warp; u < nunits; u += WPB) {
        const int r = chunk + (u >> 2);
        const int q = u & 3;
        const float4* wh = (const float4*)(W_hh + (size_t)r * HDIM) + (q << 7) + lane;
        const float4* hv = (const float4*)sh_h + (q << 7) + lane;
        const float*  wi = W_ih + (size_t)r * (IDIM + 1) + 1 + (q << 8) + lane;
        const float*  xs = sh_x + (q << 8) + lane;

        // flat load batch: 4x LDG.128 + 8x LDG.32
        float4 w0 = __ldg(wh);
        float4 w1 = __ldg(wh + 32);
        float4 w2 = __ldg(wh + 64);
        float4 w3 = __ldg(wh + 96);
        float i0 = __ldg(wi);
        float i1 = __ldg(wi + 32);
        float i2 = __ldg(wi + 64);
        float i3 = __ldg(wi + 96);
        float i4 = __ldg(wi + 128);
        float i5 = __ldg(wi + 160);
        float i6 = __ldg(wi + 192);
        float i7 = __ldg(wi + 224);

        float4 hA = hv[0], hB = hv[32], hC = hv[64], hD = hv[96];
        float hh = (dot4(w0, hA) + dot4(w1, hB)) + (dot4(w2, hC) + dot4(w3, hD));
        float ih = ((i0 * xs[0] + i1 * xs[32]) + (i2 * xs[64] + i3 * xs[96]))
                 + ((i4 * xs[128] + i5 * xs[160]) + (i6 * xs[192] + i7 * xs[224]));

        hh = warp_reduce(hh);
        ih = warp_reduce(ih);
        if (lane == 0) { s_hh[u] = hh; s_ih[u] = ih; }
    }
    __syncthreads();
    if (tid < nrows) {
        const int r = chunk + tid;
        float ih = (s_ih[4 * tid] + s_ih[4 * tid + 1])
                 + (s_ih[4 * tid + 2] + s_ih[4 * tid + 3])
                 + b_ih[r] + b_hh[r];
        float hh = (s_hh[4 * tid] + s_hh[4 * tid + 1])
                 + (s_hh[4 * tid + 2] + s_hh[4 * tid + 3]);
        g_gx_buf[r] = ih;
        g_gates[0][r] = ih + __ldg(W_ih + (size_t)r * (IDIM + 1)) + hh;  // +flag col
    }
    grid_sync();

    // ---- adaptive loop: ONE grid barrier per step ----
    float cum = 0.0f;
    int   halted_t = MAX_STEPS - 1;
    int   buf = 0;

    for (int t = 0; t < MAX_STEPS; ++t) {
        // phase B: activations + halt (redundant per block)
        const float* gt = g_gates[buf];
        float part = 0.0f;
        #pragma unroll
        for (int j = tid; j < HDIM; j += NTHREAD) {
            float gi = gt[j];
            float gf = gt[HDIM + j];
            float gg = gt[2 * HDIM + j];
            float go = gt[3 * HDIM + j];
            float cn = sigmoidf_(gf) * sh_c[j] + sigmoidf_(gi) * tanhf(gg);
            float hn = sigmoidf_(go) * tanhf(cn);
            sh_c[j] = cn;
            sh_h[j] = hn;
            part += w_halt[j] * hn;
        }
        part = warp_reduce(part);
        if (lane == 0) s_red[warp] = part;
        __syncthreads();
        float dot = 0.0f;
        #pragma unroll
        for (int w2 = 0; w2 < WPB; ++w2) dot += s_red[w2];
        float p = sigmoidf_(dot + bh);
        cum += p;
        if (cum >= 0.99f || t == MAX_STEPS - 1) { halted_t = t; break; }

        // phase A for step t+1: gates = gx + W_hh @ h  (quarter-row units)
        buf ^= 1;
        float* gn = g_gates[buf];
        for (int u = warp; u < nunits; u += WPB) {
            const int r = chunk + (u >> 2);
            const int q = u & 3;
            const float4* wh = (const float4*)(W_hh + (size_t)r * HDIM) + (q << 7) + lane;
            const float4* hv = (const float4*)sh_h + (q << 7) + lane;
            float4 w0 = __ldg(wh);
            float4 w1 = __ldg(wh + 32);
            float4 w2 = __ldg(wh + 64);
            float4 w3 = __ldg(wh + 96);
            float4 hA = hv[0], hB = hv[32], hC = hv[64], hD = hv[96];
            float hh = (dot4(w0, hA) + dot4(w1, hB)) + (dot4(w2, hC) + dot4(w3, hD));
            hh = warp_reduce(hh);
            if (lane == 0) s_hh[u] = hh;
        }
        __syncthreads();
        if (tid < nrows) {
            const int r = chunk + tid;
            gn[r] = g_gx_buf[r]
                  + (s_hh[4 * tid] + s_hh[4 * tid + 1])
                  + (s_hh[4 * tid + 2] + s_hh[4 * tid + 3]);
        }
        grid_sync();
    }

    // ---- epilogue (barrier-free): out = W_out @ h + b_out ----
    // 1024 rows over 148 blocks: 136 blocks x 7 rows, 12 x 6. One quarter-unit/warp.
    __syncthreads();
    {
        const int orows  = 6 + (bx < 136 ? 1 : 0);
        const int ostart = bx * 6 + (bx < 136 ? bx : 136);
        const int ounits = orows * 4;      // 24 or 28 <= 32
        if (warp < ounits) {
            const int row = ostart + (warp >> 2);
            const int q   = warp & 3;
            const float4* wr = (const float4*)(W_out + (size_t)row * HDIM) + (q << 7) + lane;
            const float4* hv = (const float4*)sh_h + (q << 7) + lane;
            float4 w0 = __ldg(wr);
            float4 w1 = __ldg(wr + 32);
            float4 w2 = __ldg(wr + 64);
            float4 w3 = __ldg(wr + 96);
            float4 hA = hv[0], hB = hv[32], hC = hv[64], hD = hv[96];
            float a = (dot4(w0, hA) + dot4(w1, hB)) + (dot4(w2, hC) + dot4(w3, hD));
            a = warp_reduce(a);
            if (lane == 0) s_hh[warp] = a;
        }
        __syncthreads();
        if (tid < orows) {
            const int row = ostart + tid;
            out[row] = (s_hh[4 * tid] + s_hh[4 * tid + 1])
                     + (s_hh[4 * tid + 2] + s_hh[4 * tid + 3]) + b_out[row];
        }
    }

    if (bx == 0) {
        for (int j = tid; j < HDIM; j += NTHREAD) {
            out[ODIM + j]        = sh_h[j];
            out[ODIM + HDIM + j] = sh_c[j];
        }
        if (tid == 0) out[ODIM + 2 * HDIM] = (float)halted_t;
    }
}

extern "C" void kernel_launch(void* const* d_in, const int* in_sizes, int n_in,
                              void* d_out, int out_size) {
    (void)in_sizes; (void)n_in; (void)out_size;
    const float* x      = (const float*)d_in[0];
    const float* h0     = (const float*)d_in[1];
    const float* c0     = (const float*)d_in[2];
    const float* W_ih   = (const float*)d_in[3];
    const float* W_hh   = (const float*)d_in[4];
    const float* b_ih   = (const float*)d_in[5];
    const float* b_hh   = (const float*)d_in[6];
    const float* w_halt = (const float*)d_in[7];
    const float* b_halt = (const float*)d_in[8];
    const float* W_out  = (const float*)d_in[9];
    const float* b_out  = (const float*)d_in[10];
    float* out = (float*)d_out;

    act_lstm_kernel<<<NBLOCK, NTHREAD>>>(x, h0, c0, W_ih, W_hh, b_ih, b_hh,
                                         w_halt, b_halt, W_out, b_out, out);
}